// round 14
// baseline (speedup 1.0000x reference)
#include <cuda_runtime.h>
#include <math_constants.h>

// ---- problem constants ----
#define BG     4
#define NN     16384
#define KK     8192
#define KNN    6
#define TOTK   32768
#define EE     196608

// output section offsets (float32 elements)
#define OFF_XC    0
#define OFF_POSC  4194304
#define OFF_EA    4292608
#define OFF_EI    5865472
#define OFF_PERM  6651904
#define OFF_NT    6684672
#define OFF_BATCH 6717440

__device__ int    g_perm[TOTK];
__device__ float4 g_posc[TOTK];   // x,y,z, sq

// Reference d2 rounding (bit-exact, verified R13):
//   sq  = fma(z,z, fma(x,x, fl(y*y)))
//   dot = fma(z,cz, fma(y,cy, fl(x*cx)))
//   d2  = fl( fl(sq_i + sq_j) - fl(2*dot) )
__device__ __forceinline__ float d2_ref(float4 a, float4 b) {
    float t = __fmul_rn(a.x, b.x);
    t = __fmaf_rn(a.y, b.y, t);
    t = __fmaf_rn(a.z, b.z, t);
    return __fsub_rn(__fadd_rn(a.w, b.w), __fadd_rn(t, t));
}
__device__ __forceinline__ float sq_ref(float px, float py, float pz) {
    return __fmaf_rn(pz, pz, __fmaf_rn(px, px, __fmul_rn(py, py)));
}

// ---------------------------------------------------------------------------
// Kernel 1: per-graph stable LSD radix sort (4x8-bit) of orderable-descending
// scores with u16 index payload. Stable ascending sort on ud=~orderable(score)
// == descending score, ties lower-index first — identical output to the
// verified bitonic (keys unique). Then epilogue: perm/pos_c/sq/nt/batch.
//
// smem layout (bytes): k0[16384]u32 | k1[16384]u32 | p0[16384]u16 |
//                      p1[16384]u16 | hist[32][256]u32 | dtot[256]u32
// total = 65536*2 + 32768*2 + 32768 + 1024 = 230400
// ---------------------------------------------------------------------------
#define TK_SMEM 230400
extern __shared__ unsigned char s_raw[];

__global__ void topk_kernel(const float* __restrict__ attn,
                            const float* __restrict__ pos,
                            const int*   __restrict__ node_type,
                            float* __restrict__ out) {
    const int g    = blockIdx.x;
    const int tid  = threadIdx.x;
    const int lane = tid & 31;
    const int w    = tid >> 5;

    unsigned*       k0   = (unsigned*)s_raw;
    unsigned*       k1   = k0 + NN;
    unsigned short* p0   = (unsigned short*)(k1 + NN);
    unsigned short* p1   = p0 + NN;
    unsigned*       hist = (unsigned*)(p1 + NN);   // [32][256]
    unsigned*       dtot = hist + 32 * 256;        // [256]

    // load keys: ud ascending == score descending
    for (int i = tid; i < NN; i += 1024) {
        unsigned u = __float_as_uint(attn[g * NN + i]);
        u = (u & 0x80000000u) ? ~u : (u | 0x80000000u);
        k0[i] = ~u;
        p0[i] = (unsigned short)i;
    }
    __syncthreads();

    unsigned*       ksrc = k0, *kdst = k1;
    unsigned short* psrc = p0, *pdst = p1;

    for (int pass = 0; pass < 4; pass++) {
        const int sh = pass * 8;

        for (int i = tid; i < 32 * 256; i += 1024) hist[i] = 0;
        __syncthreads();

        // count (warp w owns items [w*512, w*512+512))
        for (int s = 0; s < 16; s++) {
            int it = (w << 9) + (s << 5) + lane;
            unsigned d = (ksrc[it] >> sh) & 255u;
            unsigned mask = __match_any_sync(0xFFFFFFFFu, d);
            int leader = __ffs(mask) - 1;
            if (lane == leader) hist[(w << 8) + d] += __popc(mask);
            __syncwarp();
        }
        __syncthreads();

        // per-digit: exclusive prefix over warps; dtot = digit totals
        if (tid < 256) {
            unsigned sum = 0;
            for (int ww = 0; ww < 32; ww++) {
                unsigned c = hist[(ww << 8) + tid];
                hist[(ww << 8) + tid] = sum;
                sum += c;
            }
            dtot[tid] = sum;
        }
        __syncthreads();

        // inclusive scan of dtot[256] (Hillis-Steele)
        for (int off = 1; off < 256; off <<= 1) {
            unsigned v = 0;
            if (tid < 256 && tid >= off) v = dtot[tid - off];
            __syncthreads();
            if (tid < 256 && tid >= off) dtot[tid] += v;
            __syncthreads();
        }

        // hist[w][d] += exclusive digit base
        for (int i = tid; i < 32 * 256; i += 1024) {
            int d = i & 255;
            unsigned base = (d == 0) ? 0u : dtot[d - 1];
            hist[i] += base;
        }
        __syncthreads();

        // stable scatter
        for (int s = 0; s < 16; s++) {
            int it = (w << 9) + (s << 5) + lane;
            unsigned key = ksrc[it];
            unsigned short pay = psrc[it];
            unsigned d = (key >> sh) & 255u;
            unsigned mask = __match_any_sync(0xFFFFFFFFu, d);
            int leader = __ffs(mask) - 1;
            int prior  = __popc(mask & ((1u << lane) - 1u));
            unsigned base = 0;
            if (lane == leader) {
                base = hist[(w << 8) + d];
                hist[(w << 8) + d] = base + __popc(mask);
            }
            base = __shfl_sync(0xFFFFFFFFu, base, leader);
            unsigned ppos = base + prior;
            kdst[ppos] = key;
            pdst[ppos] = pay;
            __syncwarp();
        }
        __syncthreads();

        unsigned* kt = ksrc; ksrc = kdst; kdst = kt;
        unsigned short* pt = psrc; psrc = pdst; pdst = pt;
    }

    // epilogue: ranks 0..KK-1 (4 passes => result back in k0/p0 == ksrc)
    for (int r = tid; r < KK; r += 1024) {
        int il  = (int)psrc[r];
        int pv  = g * NN + il;
        int row = g * KK + r;
        g_perm[row] = pv;
        out[OFF_PERM + row] = (float)pv;

        float px = pos[pv * 3 + 0];
        float py = pos[pv * 3 + 1];
        float pz = pos[pv * 3 + 2];
        out[OFF_POSC + row * 3 + 0] = px;
        out[OFF_POSC + row * 3 + 1] = py;
        out[OFF_POSC + row * 3 + 2] = pz;

        g_posc[row] = make_float4(px, py, pz, sq_ref(px, py, pz));

        out[OFF_NT + row]    = (float)node_type[pv];
        out[OFF_BATCH + row] = (float)g;
    }
}

// ---------------------------------------------------------------------------
// Kernel 2: x_c = x[perm] @ W^T + b   (bit-exact ✓, unchanged)
// ---------------------------------------------------------------------------
__global__ void gemm_kernel(const float* __restrict__ x,
                            const float* __restrict__ W,
                            const float* __restrict__ bias,
                            float* __restrict__ out) {
    __shared__ float Wsh[64 * 129];
    __shared__ float xs[16 * 64];
    __shared__ int   rows[16];

    const int t  = threadIdx.x;
    const int m0 = blockIdx.x * 16;

    if (t < 16) rows[t] = g_perm[m0 + t];

    float acc[16];
#pragma unroll
    for (int r = 0; r < 16; r++) acc[r] = 0.f;

    for (int kc = 0; kc < 2; kc++) {
        const int k0 = kc * 64;
        __syncthreads();
#pragma unroll
        for (int it = 0; it < 64; it++) {
            int idx = it * 128 + t;
            int c = idx >> 6;
            int k = idx & 63;
            Wsh[k * 129 + c] = W[c * 128 + k0 + k];
        }
#pragma unroll
        for (int it = 0; it < 8; it++) {
            int idx = it * 128 + t;
            int r = idx >> 6;
            int k = idx & 63;
            xs[r * 64 + k] = x[rows[r] * 128 + k0 + k];
        }
        __syncthreads();
#pragma unroll
        for (int k = 0; k < 64; k++) {
            float wv = Wsh[k * 129 + t];
#pragma unroll
            for (int r = 0; r < 16; r++)
                acc[r] = fmaf(xs[r * 64 + k], wv, acc[r]);
        }
    }

    float bb = bias[t];
#pragma unroll
    for (int r = 0; r < 16; r++)
        out[OFF_XC + (m0 + r) * 128 + t] = acc[r] + bb;
}

// ---------------------------------------------------------------------------
// Kernel 3: KNN, 2 queries per thread (shared candidate LDS), 128 thr/CTA,
// 128 CTAs (1 per SM). d2 per d2_ref; stable lower-index ties.
// ---------------------------------------------------------------------------
__global__ void knn_kernel(float* __restrict__ out) {
    __shared__ float4 sh[2048];

    const int g    = blockIdx.x >> 5;                     // 32 CTAs / graph
    const int q0   = ((blockIdx.x & 31) << 7) + threadIdx.x;  // 0..4095
    const int q1   = q0 + 4096;
    const int base = g * KK;

    const float4 qa = g_posc[base + q0];
    const float4 qb = g_posc[base + q1];

    float bda[6], bdb[6];
    int   bia[6], bib[6];
#pragma unroll
    for (int m = 0; m < 6; m++) {
        bda[m] = CUDART_INF_F; bia[m] = 0;
        bdb[m] = CUDART_INF_F; bib[m] = 0;
    }

    for (int t0 = 0; t0 < KK; t0 += 2048) {
        __syncthreads();
        for (int j = threadIdx.x; j < 2048; j += 128)
            sh[j] = g_posc[base + t0 + j];
        __syncthreads();

#pragma unroll 4
        for (int j = 0; j < 2048; j++) {
            float4 c  = sh[j];
            int    jl = t0 + j;

            float da = d2_ref(qa, c);
            if (jl != q0 && da < bda[5]) {
                bda[5] = da; bia[5] = jl;
#pragma unroll
                for (int m = 5; m > 0; m--) {
                    if (bda[m] < bda[m - 1]) {
                        float td = bda[m]; bda[m] = bda[m - 1]; bda[m - 1] = td;
                        int   ti = bia[m]; bia[m] = bia[m - 1]; bia[m - 1] = ti;
                    }
                }
            }

            float db = d2_ref(qb, c);
            if (jl != q1 && db < bdb[5]) {
                bdb[5] = db; bib[5] = jl;
#pragma unroll
                for (int m = 5; m > 0; m--) {
                    if (bdb[m] < bdb[m - 1]) {
                        float td = bdb[m]; bdb[m] = bdb[m - 1]; bdb[m - 1] = td;
                        int   ti = bib[m]; bib[m] = bib[m - 1]; bib[m - 1] = ti;
                    }
                }
            }
        }
    }

    // emit for both queries
#pragma unroll
    for (int sel = 0; sel < 2; sel++) {
        const int    q  = sel ? q1 : q0;
        const float4 qp = sel ? qb : qa;
        const int*   bi = sel ? bib : bia;
        const int    ig = base + q;
#pragma unroll
        for (int k = 0; k < KNN; k++) {
            int send = base + bi[k];
            int e    = ig * KNN + k;
            float4 ps = g_posc[send];
            float rx = __fsub_rn(ps.x, qp.x);
            float ry = __fsub_rn(ps.y, qp.y);
            float rz = __fsub_rn(ps.z, qp.z);
            float ss = __fmaf_rn(rz, rz, __fmaf_rn(rx, rx, __fmul_rn(ry, ry)));
            float nrm = sqrtf(ss);

            int ea0 = OFF_EA + e * 4;
            out[ea0 + 0] = rx;  out[ea0 + 1] = ry;  out[ea0 + 2] = rz;  out[ea0 + 3] = nrm;
            int ea1 = OFF_EA + (EE + e) * 4;
            out[ea1 + 0] = -rx; out[ea1 + 1] = -ry; out[ea1 + 2] = -rz; out[ea1 + 3] = nrm;

            out[OFF_EI + e]          = (float)send;
            out[OFF_EI + EE + e]     = (float)ig;
            out[OFF_EI + 2 * EE + e] = (float)ig;
            out[OFF_EI + 3 * EE + e] = (float)send;
        }
    }
}

// ---------------------------------------------------------------------------
extern "C" void kernel_launch(void* const* d_in, const int* in_sizes, int n_in,
                              void* d_out, int out_size) {
    const float* x         = (const float*)d_in[0];
    const float* pos       = (const float*)d_in[1];
    const float* attn      = (const float*)d_in[2];
    const float* W         = (const float*)d_in[3];
    const float* b         = (const float*)d_in[4];
    const int*   node_type = (const int*)d_in[5];
    float* out = (float*)d_out;

    cudaFuncSetAttribute(topk_kernel,
                         cudaFuncAttributeMaxDynamicSharedMemorySize, TK_SMEM);

    topk_kernel<<<BG, 1024, TK_SMEM>>>(attn, pos, node_type, out);
    gemm_kernel<<<TOTK / 16, 128>>>(x, W, b, out);
    knn_kernel<<<128, 128>>>(out);
}

// round 16
// speedup vs baseline: 1.4547x; 1.4547x over previous
#include <cuda_runtime.h>
#include <math_constants.h>

// ---- problem constants ----
#define BG     4
#define NN     16384
#define KK     8192
#define KNN    6
#define TOTK   32768
#define EE     196608

// output section offsets (float32 elements)
#define OFF_XC    0
#define OFF_POSC  4194304
#define OFF_EA    4292608
#define OFF_EI    5865472
#define OFF_PERM  6651904
#define OFF_NT    6684672
#define OFF_BATCH 6717440

__device__ int                g_perm[TOTK];
__device__ float4             g_posc[TOTK];          // x,y,z, sq
__device__ unsigned long long g_keys[BG * NN];       // sorted 2048-runs

// Reference d2 rounding (bit-exact, verified R13):
__device__ __forceinline__ float d2_ref(float4 a, float4 b) {
    float t = __fmul_rn(a.x, b.x);
    t = __fmaf_rn(a.y, b.y, t);
    t = __fmaf_rn(a.z, b.z, t);
    return __fsub_rn(__fadd_rn(a.w, b.w), __fadd_rn(t, t));
}
__device__ __forceinline__ float sq_ref(float px, float py, float pz) {
    return __fmaf_rn(pz, pz, __fmaf_rn(px, px, __fmul_rn(py, py)));
}

// ---------------------------------------------------------------------------
// Kernel 1a: chunk sort. 32 CTAs (8 per graph), each bitonic-sorts 2048 u64
// keys  key = (~orderable(score) << 16) | local_idx  (unique) ascending
// == score descending, ties lower-index. Writes sorted runs to g_keys.
// ---------------------------------------------------------------------------
__global__ void chunk_sort_kernel(const float* __restrict__ attn) {
    __shared__ unsigned long long sk[2048];

    const int g   = blockIdx.x >> 3;
    const int c   = blockIdx.x & 7;
    const int tid = threadIdx.x;

    for (int i = tid; i < 2048; i += 256) {
        int il = (c << 11) + i;                       // local node idx 0..16383
        unsigned u = __float_as_uint(attn[g * NN + il]);
        u = (u & 0x80000000u) ? ~u : (u | 0x80000000u);
        sk[i] = ((unsigned long long)(~u) << 16) | (unsigned)il;
    }
    __syncthreads();

    for (int k = 2; k <= 2048; k <<= 1) {
        for (int j = k >> 1; j > 0; j >>= 1) {
            for (int i = tid; i < 2048; i += 256) {
                int ixj = i ^ j;
                if (ixj > i) {
                    unsigned long long a = sk[i];
                    unsigned long long b = sk[ixj];
                    bool up = ((i & k) == 0);
                    if ((a > b) == up) { sk[i] = b; sk[ixj] = a; }
                }
            }
            __syncthreads();
        }
    }

    for (int i = tid; i < 2048; i += 256)
        g_keys[g * NN + (c << 11) + i] = sk[i];
}

// ---------------------------------------------------------------------------
// Kernel 1b: rank + epilogue. One thread per element: global rank = offset in
// own run + sum of lower_bound over the 7 sibling runs (unique keys => exact).
// rank < KK  ->  write perm / pos_c / g_posc(sq) / node_type_c / batch_c.
// ---------------------------------------------------------------------------
__global__ void rank_kernel(const float* __restrict__ pos,
                            const int*   __restrict__ node_type,
                            float* __restrict__ out) {
    const int t = blockIdx.x * 256 + threadIdx.x;     // 0..65535
    const int g = t >> 14;
    const int p = t & (NN - 1);

    const unsigned long long* keys = g_keys + g * NN;
    const unsigned long long  v    = keys[p];
    const int myrun = p >> 11;

    int rank = p & 2047;
#pragma unroll
    for (int r = 0; r < 8; r++) {
        if (r == myrun) continue;
        const unsigned long long* R = keys + (r << 11);
        int lo = 0, hi = 2048;
#pragma unroll
        for (int it = 0; it < 12; it++) {             // 12 = iterations to close [0,2048]
            if (lo < hi) {
                int mid = (lo + hi) >> 1;
                if (R[mid] < v) lo = mid + 1; else hi = mid;
            }
        }
        rank += lo;
    }

    if (rank < KK) {
        int il  = (int)(v & 0xFFFFull);
        int pv  = g * NN + il;
        int row = g * KK + rank;
        g_perm[row] = pv;
        out[OFF_PERM + row] = (float)pv;

        float px = pos[pv * 3 + 0];
        float py = pos[pv * 3 + 1];
        float pz = pos[pv * 3 + 2];
        out[OFF_POSC + row * 3 + 0] = px;
        out[OFF_POSC + row * 3 + 1] = py;
        out[OFF_POSC + row * 3 + 2] = pz;

        g_posc[row] = make_float4(px, py, pz, sq_ref(px, py, pz));

        out[OFF_NT + row]    = (float)node_type[pv];
        out[OFF_BATCH + row] = (float)g;
    }
}

// ---------------------------------------------------------------------------
// Kernel 2: x_c = x[perm] @ W^T + b   (bit-exact ✓, unchanged)
// ---------------------------------------------------------------------------
__global__ void gemm_kernel(const float* __restrict__ x,
                            const float* __restrict__ W,
                            const float* __restrict__ bias,
                            float* __restrict__ out) {
    __shared__ float Wsh[64 * 129];
    __shared__ float xs[16 * 64];
    __shared__ int   rows[16];

    const int t  = threadIdx.x;
    const int m0 = blockIdx.x * 16;

    if (t < 16) rows[t] = g_perm[m0 + t];

    float acc[16];
#pragma unroll
    for (int r = 0; r < 16; r++) acc[r] = 0.f;

    for (int kc = 0; kc < 2; kc++) {
        const int k0 = kc * 64;
        __syncthreads();
#pragma unroll
        for (int it = 0; it < 64; it++) {
            int idx = it * 128 + t;
            int c = idx >> 6;
            int k = idx & 63;
            Wsh[k * 129 + c] = W[c * 128 + k0 + k];
        }
#pragma unroll
        for (int it = 0; it < 8; it++) {
            int idx = it * 128 + t;
            int r = idx >> 6;
            int k = idx & 63;
            xs[r * 64 + k] = x[rows[r] * 128 + k0 + k];
        }
        __syncthreads();
#pragma unroll
        for (int k = 0; k < 64; k++) {
            float wv = Wsh[k * 129 + t];
#pragma unroll
            for (int r = 0; r < 16; r++)
                acc[r] = fmaf(xs[r * 64 + k], wv, acc[r]);
        }
    }

    float bb = bias[t];
#pragma unroll
    for (int r = 0; r < 16; r++)
        out[OFF_XC + (m0 + r) * 128 + t] = acc[r] + bb;
}

// ---------------------------------------------------------------------------
// Kernel 3: KNN split-candidate. 2 threads per query (half = tid&1), each
// scans candidates [half*4096, half*4096+4096). Per-half top-6 with strict '<'
// (stable lower-index within its range). Halves have disjoint ascending index
// ranges -> exact merge: on d2 tie take half-A (lower indices).
// 512 CTAs x 128 threads = 64 queries/CTA.
// ---------------------------------------------------------------------------
__global__ void knn_kernel(float* __restrict__ out) {
    __shared__ float4 sh[2048];                       // [0:1024)=A, [1024:2048)=B

    const int g    = blockIdx.x >> 7;                 // 128 CTAs per graph
    const int qloc = ((blockIdx.x & 127) << 6) + (threadIdx.x >> 1);
    const int half = threadIdx.x & 1;
    const int base = g * KK;
    const int q    = qloc;                            // local query 0..8191

    const float4 qp = g_posc[base + q];

    float bd[6];
    int   bi[6];
#pragma unroll
    for (int m = 0; m < 6; m++) { bd[m] = CUDART_INF_F; bi[m] = 0; }

    const int hoff = half << 12;                      // 0 or 4096

    for (int t0 = 0; t0 < 4096; t0 += 1024) {
        __syncthreads();
        for (int j = threadIdx.x; j < 2048; j += 128) {
            int h = j >> 10;                          // which half this slot holds
            sh[j] = g_posc[base + (h << 12) + t0 + (j & 1023)];
        }
        __syncthreads();

        const float4* ms = sh + (half << 10);
#pragma unroll 4
        for (int j = 0; j < 1024; j++) {
            float4 c  = ms[j];
            int    jl = hoff + t0 + j;
            float d2 = d2_ref(qp, c);
            if (jl != q && d2 < bd[5]) {
                bd[5] = d2; bi[5] = jl;
#pragma unroll
                for (int m = 5; m > 0; m--) {
                    if (bd[m] < bd[m - 1]) {
                        float td = bd[m]; bd[m] = bd[m - 1]; bd[m - 1] = td;
                        int   ti = bi[m]; bi[m] = bi[m - 1]; bi[m - 1] = ti;
                    }
                }
            }
        }
    }

    // exchange partner's list (lane^1) and merge on the even (half-A) lane
    float pd[6];
    int   pi[6];
#pragma unroll
    for (int m = 0; m < 6; m++) {
        pd[m] = __shfl_xor_sync(0xFFFFFFFFu, bd[m], 1);
        pi[m] = __shfl_xor_sync(0xFFFFFFFFu, bi[m], 1);
    }

    if (half == 0) {
        // mine = A (indices 0..4095), partner = B (4096..8191)
        float md[6]; int mi[6];
        int ia = 0, ib = 0;
#pragma unroll
        for (int k = 0; k < 6; k++) {
            if (bd[ia] <= pd[ib]) { md[k] = bd[ia]; mi[k] = bi[ia]; ia++; }
            else                  { md[k] = pd[ib]; mi[k] = pi[ib]; ib++; }
        }

        const int ig = base + q;
#pragma unroll
        for (int k = 0; k < KNN; k++) {
            int send = base + mi[k];
            int e    = ig * KNN + k;
            float4 ps = g_posc[send];
            float rx = __fsub_rn(ps.x, qp.x);
            float ry = __fsub_rn(ps.y, qp.y);
            float rz = __fsub_rn(ps.z, qp.z);
            float ss = __fmaf_rn(rz, rz, __fmaf_rn(rx, rx, __fmul_rn(ry, ry)));
            float nrm = sqrtf(ss);

            int ea0 = OFF_EA + e * 4;
            out[ea0 + 0] = rx;  out[ea0 + 1] = ry;  out[ea0 + 2] = rz;  out[ea0 + 3] = nrm;
            int ea1 = OFF_EA + (EE + e) * 4;
            out[ea1 + 0] = -rx; out[ea1 + 1] = -ry; out[ea1 + 2] = -rz; out[ea1 + 3] = nrm;

            out[OFF_EI + e]          = (float)send;
            out[OFF_EI + EE + e]     = (float)ig;
            out[OFF_EI + 2 * EE + e] = (float)ig;
            out[OFF_EI + 3 * EE + e] = (float)send;
        }
    }
}

// ---------------------------------------------------------------------------
extern "C" void kernel_launch(void* const* d_in, const int* in_sizes, int n_in,
                              void* d_out, int out_size) {
    const float* x         = (const float*)d_in[0];
    const float* pos       = (const float*)d_in[1];
    const float* attn      = (const float*)d_in[2];
    const float* W         = (const float*)d_in[3];
    const float* b         = (const float*)d_in[4];
    const int*   node_type = (const int*)d_in[5];
    float* out = (float*)d_out;

    chunk_sort_kernel<<<32, 256>>>(attn);
    rank_kernel<<<BG * NN / 256, 256>>>(pos, node_type, out);
    gemm_kernel<<<TOTK / 16, 128>>>(x, W, b, out);
    knn_kernel<<<512, 128>>>(out);
}

// round 17
// speedup vs baseline: 2.0662x; 1.4204x over previous
#include <cuda_runtime.h>
#include <math_constants.h>

// ---- problem constants ----
#define BG     4
#define NN     16384
#define KK     8192
#define KNN    6
#define TOTK   32768
#define EE     196608

// output section offsets (float32 elements)
#define OFF_XC    0
#define OFF_POSC  4194304
#define OFF_EA    4292608
#define OFF_EI    5865472
#define OFF_PERM  6651904
#define OFF_NT    6684672
#define OFF_BATCH 6717440

__device__ int                g_perm[TOTK];
__device__ float4             g_posc[TOTK];          // x,y,z, sq
__device__ unsigned long long g_keys[BG * NN];       // sorted 2048-runs

// Reference d2 rounding (bit-exact, verified R13):
__device__ __forceinline__ float d2_ref(float4 a, float4 b) {
    float t = __fmul_rn(a.x, b.x);
    t = __fmaf_rn(a.y, b.y, t);
    t = __fmaf_rn(a.z, b.z, t);
    return __fsub_rn(__fadd_rn(a.w, b.w), __fadd_rn(t, t));
}
__device__ __forceinline__ float sq_ref(float px, float py, float pz) {
    return __fmaf_rn(pz, pz, __fmaf_rn(px, px, __fmul_rn(py, py)));
}

// ---------------------------------------------------------------------------
// Kernel 1a: chunk sort (32 CTAs, 1024 threads). Bitonic-sorts 2048 u64 keys
// key = (~orderable(score)<<16)|idx ascending == score desc, ties lower-idx.
// ---------------------------------------------------------------------------
__global__ void chunk_sort_kernel(const float* __restrict__ attn) {
    __shared__ unsigned long long sk[2048];

    const int g   = blockIdx.x >> 3;
    const int c   = blockIdx.x & 7;
    const int tid = threadIdx.x;

    for (int i = tid; i < 2048; i += 1024) {
        int il = (c << 11) + i;
        unsigned u = __float_as_uint(attn[g * NN + il]);
        u = (u & 0x80000000u) ? ~u : (u | 0x80000000u);
        sk[i] = ((unsigned long long)(~u) << 16) | (unsigned)il;
    }
    __syncthreads();

    for (int k = 2; k <= 2048; k <<= 1) {
        for (int j = k >> 1; j > 0; j >>= 1) {
            for (int i = tid; i < 2048; i += 1024) {
                int ixj = i ^ j;
                if (ixj > i) {
                    unsigned long long a = sk[i];
                    unsigned long long b = sk[ixj];
                    bool up = ((i & k) == 0);
                    if ((a > b) == up) { sk[i] = b; sk[ixj] = a; }
                }
            }
            __syncthreads();
        }
    }

    for (int i = tid; i < 2048; i += 1024)
        g_keys[g * NN + (c << 11) + i] = sk[i];
}

// ---------------------------------------------------------------------------
// Kernel 1b: rank + epilogue (verified R16).
// ---------------------------------------------------------------------------
__global__ void rank_kernel(const float* __restrict__ pos,
                            const int*   __restrict__ node_type,
                            float* __restrict__ out) {
    const int t = blockIdx.x * 256 + threadIdx.x;
    const int g = t >> 14;
    const int p = t & (NN - 1);

    const unsigned long long* keys = g_keys + g * NN;
    const unsigned long long  v    = keys[p];
    const int myrun = p >> 11;

    int rank = p & 2047;
#pragma unroll
    for (int r = 0; r < 8; r++) {
        if (r == myrun) continue;
        const unsigned long long* R = keys + (r << 11);
        int lo = 0, hi = 2048;
#pragma unroll
        for (int it = 0; it < 12; it++) {
            if (lo < hi) {
                int mid = (lo + hi) >> 1;
                if (R[mid] < v) lo = mid + 1; else hi = mid;
            }
        }
        rank += lo;
    }

    if (rank < KK) {
        int il  = (int)(v & 0xFFFFull);
        int pv  = g * NN + il;
        int row = g * KK + rank;
        g_perm[row] = pv;
        out[OFF_PERM + row] = (float)pv;

        float px = pos[pv * 3 + 0];
        float py = pos[pv * 3 + 1];
        float pz = pos[pv * 3 + 2];
        out[OFF_POSC + row * 3 + 0] = px;
        out[OFF_POSC + row * 3 + 1] = py;
        out[OFF_POSC + row * 3 + 2] = pz;

        g_posc[row] = make_float4(px, py, pz, sq_ref(px, py, pz));

        out[OFF_NT + row]    = (float)node_type[pv];
        out[OFF_BATCH + row] = (float)g;
    }
}

// ---------------------------------------------------------------------------
// Kernel 2: x_c = x[perm] @ W^T + b   (bit-exact ✓, unchanged)
// ---------------------------------------------------------------------------
__global__ void gemm_kernel(const float* __restrict__ x,
                            const float* __restrict__ W,
                            const float* __restrict__ bias,
                            float* __restrict__ out) {
    __shared__ float Wsh[64 * 129];
    __shared__ float xs[16 * 64];
    __shared__ int   rows[16];

    const int t  = threadIdx.x;
    const int m0 = blockIdx.x * 16;

    if (t < 16) rows[t] = g_perm[m0 + t];

    float acc[16];
#pragma unroll
    for (int r = 0; r < 16; r++) acc[r] = 0.f;

    for (int kc = 0; kc < 2; kc++) {
        const int k0 = kc * 64;
        __syncthreads();
#pragma unroll
        for (int it = 0; it < 64; it++) {
            int idx = it * 128 + t;
            int c = idx >> 6;
            int k = idx & 63;
            Wsh[k * 129 + c] = W[c * 128 + k0 + k];
        }
#pragma unroll
        for (int it = 0; it < 8; it++) {
            int idx = it * 128 + t;
            int r = idx >> 6;
            int k = idx & 63;
            xs[r * 64 + k] = x[rows[r] * 128 + k0 + k];
        }
        __syncthreads();
#pragma unroll
        for (int k = 0; k < 64; k++) {
            float wv = Wsh[k * 129 + t];
#pragma unroll
            for (int r = 0; r < 16; r++)
                acc[r] = fmaf(xs[r * 64 + k], wv, acc[r]);
        }
    }

    float bb = bias[t];
#pragma unroll
    for (int r = 0; r < 16; r++)
        out[OFF_XC + (m0 + r) * 128 + t] = acc[r] + bb;
}

// ---------------------------------------------------------------------------
// Kernel 3: warp-cooperative ballot KNN. One warp serves 2 queries (q0 in
// [0,4096), q1 = q0+4096). 32 lanes evaluate 32 candidates in parallel; rare
// hits (ballot) are replayed by ALL lanes identically via shfl -> replicated
// top-6 in registers, zero divergence. Processing order = index ascending;
// insert gate re-checks current bd[5] -> EXACT sequential (R13) semantics.
// ---------------------------------------------------------------------------
__device__ __forceinline__ void emit_q(int base, int q, const float4 qp,
                                       const int* bi, float* __restrict__ out) {
    const int ig = base + q;
#pragma unroll
    for (int k = 0; k < KNN; k++) {
        int send = base + bi[k];
        int e    = ig * KNN + k;
        float4 ps = g_posc[send];
        float rx = __fsub_rn(ps.x, qp.x);
        float ry = __fsub_rn(ps.y, qp.y);
        float rz = __fsub_rn(ps.z, qp.z);
        float ss = __fmaf_rn(rz, rz, __fmaf_rn(rx, rx, __fmul_rn(ry, ry)));
        float nrm = sqrtf(ss);

        int ea0 = OFF_EA + e * 4;
        out[ea0 + 0] = rx;  out[ea0 + 1] = ry;  out[ea0 + 2] = rz;  out[ea0 + 3] = nrm;
        int ea1 = OFF_EA + (EE + e) * 4;
        out[ea1 + 0] = -rx; out[ea1 + 1] = -ry; out[ea1 + 2] = -rz; out[ea1 + 3] = nrm;

        out[OFF_EI + e]          = (float)send;
        out[OFF_EI + EE + e]     = (float)ig;
        out[OFF_EI + 2 * EE + e] = (float)ig;
        out[OFF_EI + 3 * EE + e] = (float)send;
    }
}

__global__ void knn_kernel(float* __restrict__ out) {
    __shared__ float4 sh[2048];

    const int g    = blockIdx.x >> 9;                 // 512 CTAs per graph
    const int cig  = blockIdx.x & 511;
    const int wid  = threadIdx.x >> 5;                // 8 warps
    const int lane = threadIdx.x & 31;
    const int base = g * KK;
    const int q0   = (cig << 3) + wid;                // 0..4095
    const int q1   = q0 + 4096;                       // 4096..8191

    const float4 qa = g_posc[base + q0];
    const float4 qb = g_posc[base + q1];

    float bdA[6], bdB[6];
    int   biA[6], biB[6];
#pragma unroll
    for (int m = 0; m < 6; m++) {
        bdA[m] = CUDART_INF_F; biA[m] = 0;
        bdB[m] = CUDART_INF_F; biB[m] = 0;
    }

    for (int t0 = 0; t0 < KK; t0 += 2048) {
        __syncthreads();
        for (int j = threadIdx.x; j < 2048; j += 256)
            sh[j] = g_posc[base + t0 + j];
        __syncthreads();

        for (int b = 0; b < 2048; b += 32) {
            const float4 c  = sh[b + lane];
            const int    jl = t0 + b + lane;

            float dA = d2_ref(qa, c);
            float dB = d2_ref(qb, c);

            unsigned mA = __ballot_sync(0xFFFFFFFFu, (dA < bdA[5]) & (jl != q0));
            unsigned mB = __ballot_sync(0xFFFFFFFFu, (dB < bdB[5]) & (jl != q1));

            while (mA) {
                int src = __ffs(mA) - 1; mA &= mA - 1;
                float dh = __shfl_sync(0xFFFFFFFFu, dA, src);
                int   ih = t0 + b + src;
                if (dh < bdA[5]) {
                    bdA[5] = dh; biA[5] = ih;
#pragma unroll
                    for (int m = 5; m > 0; m--) {
                        if (bdA[m] < bdA[m - 1]) {
                            float td = bdA[m]; bdA[m] = bdA[m - 1]; bdA[m - 1] = td;
                            int   ti = biA[m]; biA[m] = biA[m - 1]; biA[m - 1] = ti;
                        }
                    }
                }
            }
            while (mB) {
                int src = __ffs(mB) - 1; mB &= mB - 1;
                float dh = __shfl_sync(0xFFFFFFFFu, dB, src);
                int   ih = t0 + b + src;
                if (dh < bdB[5]) {
                    bdB[5] = dh; biB[5] = ih;
#pragma unroll
                    for (int m = 5; m > 0; m--) {
                        if (bdB[m] < bdB[m - 1]) {
                            float td = bdB[m]; bdB[m] = bdB[m - 1]; bdB[m - 1] = td;
                            int   ti = biB[m]; biB[m] = biB[m - 1]; biB[m - 1] = ti;
                        }
                    }
                }
            }
        }
    }

    if (lane == 0)       emit_q(base, q0, qa, biA, out);
    else if (lane == 16) emit_q(base, q1, qb, biB, out);
}

// ---------------------------------------------------------------------------
extern "C" void kernel_launch(void* const* d_in, const int* in_sizes, int n_in,
                              void* d_out, int out_size) {
    const float* x         = (const float*)d_in[0];
    const float* pos       = (const float*)d_in[1];
    const float* attn      = (const float*)d_in[2];
    const float* W         = (const float*)d_in[3];
    const float* b         = (const float*)d_in[4];
    const int*   node_type = (const int*)d_in[5];
    float* out = (float*)d_out;

    chunk_sort_kernel<<<32, 1024>>>(attn);
    rank_kernel<<<BG * NN / 256, 256>>>(pos, node_type, out);
    gemm_kernel<<<TOTK / 16, 128>>>(x, W, b, out);
    knn_kernel<<<2048, 256>>>(out);
}